// round 5
// baseline (speedup 1.0000x reference)
#include <cuda_runtime.h>
#include <math.h>

// KANLayer: IN=128, OUT=128, SIZE=16384, BATCH=1024, NUM=5, K=3 -> 8 basis fns.
// K1: basis per (b,i) once -> g_basis, silu -> g_silu (fast-math).
// K2 (fused, block-specialized):
//   bid%3==2 -> COPY block: preacts[b,o,:] = x[b,:] (pure DRAM streaming)
//   else     -> MAIN block: Q=2 outputs per basis read, postacts/postspline/y_out.

#define IN_DIM   128
#define OUT_DIM  128
#define BATCHSZ  1024
#define NB       8
#define NKNOT    12
#define TILE_B   8
#define NTHREADS 256

__device__ float g_basis[BATCHSZ * NB * IN_DIM];   // [b][j][i]
__device__ float g_silu [BATCHSZ * IN_DIM];        // [b][i]

// ---------------------------------------------------------------------------
// Kernel 1: Cox-de-Boor basis, one thread per (b,i).
// ---------------------------------------------------------------------------
__global__ __launch_bounds__(256)
void kan_basis_kernel(const float* __restrict__ x,
                      const float* __restrict__ grid)
{
    const int p = blockIdx.x * 256 + threadIdx.x;
    if (p >= BATCHSZ * IN_DIM) return;
    const int i  = p & (IN_DIM - 1);
    const float xv = x[p];

    float t[NKNOT];
    t[3] = grid[i * 6 + 0];
    t[4] = grid[i * 6 + 1];
    t[5] = grid[i * 6 + 2];
    t[6] = grid[i * 6 + 3];
    t[7] = grid[i * 6 + 4];
    t[8] = grid[i * 6 + 5];
    const float h = (t[8] - t[3]) * 0.2f;
    t[2] = t[3] - h;  t[1] = t[2] - h;  t[0]  = t[1]  - h;
    t[9] = t[8] + h;  t[10] = t[9] + h; t[11] = t[10] + h;

    float Bv[NKNOT - 1];
    #pragma unroll
    for (int m = 0; m < NKNOT - 1; m++)
        Bv[m] = (xv >= t[m] && xv < t[m + 1]) ? 1.0f : 0.0f;

    #pragma unroll
    for (int pd = 1; pd <= 3; pd++) {
        #pragma unroll
        for (int m = 0; m < NKNOT - 2; m++) {
            if (m < (NKNOT - 1) - pd) {
                const float a = __fdividef(xv - t[m],          t[m + pd] - t[m]);
                const float c = __fdividef(t[m + pd + 1] - xv, t[m + pd + 1] - t[m + 1]);
                Bv[m] = a * Bv[m] + c * Bv[m + 1];
            }
        }
    }

    const int b = p >> 7;
    #pragma unroll
    for (int j = 0; j < NB; j++)
        g_basis[(b * NB + j) * IN_DIM + i] = Bv[j];
    g_silu[p] = __fdividef(xv, 1.0f + __expf(-xv));
}

// ---------------------------------------------------------------------------
// Kernel 2: fused main + preacts-copy, block-specialized.
// grid = 1536 blocks: per group of 3 bids -> 2 MAIN + 1 COPY.
// ---------------------------------------------------------------------------
__global__ __launch_bounds__(NTHREADS, 2)
void kan_fused_kernel(const float* __restrict__ x,
                      const float* __restrict__ coef,
                      const float* __restrict__ scale_base,
                      const float* __restrict__ scale_sp,
                      const float* __restrict__ mask,
                      float* __restrict__ out)
{
    __shared__ float4 Bsh[TILE_B][NB][IN_DIM / 4];
    __shared__ float4 ssh[TILE_B][IN_DIM / 4];

    const int bid = blockIdx.x;
    const int r   = bid % 3;
    const int tid = threadIdx.x;

    const size_t P = (size_t)BATCHSZ * OUT_DIM * IN_DIM;
    float* y_out      = out;
    float* preacts    = out + (size_t)BATCHSZ * OUT_DIM;
    float* postacts   = preacts + P;
    float* postspline = postacts + P;

    if (r == 2) {
        // ================= COPY block: preacts for 2 batch rows =================
        __shared__ float4 xrow[2][IN_DIM / 4];
        const int b0c = (bid / 3) * 2;
        for (int idx = tid; idx < 2 * (IN_DIM / 4); idx += NTHREADS)
            xrow[idx >> 5][idx & 31] =
                ((const float4*)(x + (b0c + (idx >> 5)) * IN_DIM))[idx & 31];
        __syncthreads();

        #pragma unroll
        for (int b = 0; b < 2; b++) {
            float4* dst = (float4*)(preacts + (size_t)(b0c + b) * OUT_DIM * IN_DIM);
            #pragma unroll 4
            for (int k = tid; k < OUT_DIM * (IN_DIM / 4); k += NTHREADS)
                dst[k] = xrow[b][k & 31];
        }
        return;
    }

    // ================= MAIN block =================
    const int mid  = (bid / 3) * 2 + r;          // 0..1023
    const int b0   = (mid >> 3) * TILE_B;
    const int og   = mid & 7;
    const int warp = tid >> 5;
    const int L    = tid & 31;
    const int oA   = og * 16 + warp;
    const int oB   = oA + 8;

    // ---- stage basis / silu tiles ----
    {
        const float4* gb = (const float4*)(g_basis + b0 * NB * IN_DIM);
        float4* db = &Bsh[0][0][0];
        #pragma unroll
        for (int idx = tid; idx < TILE_B * NB * (IN_DIM / 4); idx += NTHREADS)
            db[idx] = gb[idx];
        const float4* gs = (const float4*)(g_silu + b0 * IN_DIM);
        float4* ds = &ssh[0][0];
        #pragma unroll
        for (int idx = tid; idx < TILE_B * (IN_DIM / 4); idx += NTHREADS)
            ds[idx] = gs[idx];
    }

    // ---- per-thread constants for both o's ----
    float cfa[4][NB], cfb[4][NB];
    float4 msbA, mssA, msbB, mssB;
    {
        const int ibase = 4 * L;
        #pragma unroll
        for (int q = 0; q < 4; q++) {
            const int sA = oA * IN_DIM + ibase + q;
            const int sB = oB * IN_DIM + ibase + q;
            float4 a0 = *(const float4*)(coef + sA * NB);
            float4 a1 = *(const float4*)(coef + sA * NB + 4);
            cfa[q][0]=a0.x; cfa[q][1]=a0.y; cfa[q][2]=a0.z; cfa[q][3]=a0.w;
            cfa[q][4]=a1.x; cfa[q][5]=a1.y; cfa[q][6]=a1.z; cfa[q][7]=a1.w;
            float4 c0 = *(const float4*)(coef + sB * NB);
            float4 c1 = *(const float4*)(coef + sB * NB + 4);
            cfb[q][0]=c0.x; cfb[q][1]=c0.y; cfb[q][2]=c0.z; cfb[q][3]=c0.w;
            cfb[q][4]=c1.x; cfb[q][5]=c1.y; cfb[q][6]=c1.z; cfb[q][7]=c1.w;
        }
        const float4 sbA = *(const float4*)(scale_base + oA * IN_DIM + ibase);
        const float4 spA = *(const float4*)(scale_sp   + oA * IN_DIM + ibase);
        const float4 mkA = *(const float4*)(mask       + oA * IN_DIM + ibase);
        msbA = make_float4(mkA.x*sbA.x, mkA.y*sbA.y, mkA.z*sbA.z, mkA.w*sbA.w);
        mssA = make_float4(mkA.x*spA.x, mkA.y*spA.y, mkA.z*spA.z, mkA.w*spA.w);
        const float4 sbB = *(const float4*)(scale_base + oB * IN_DIM + ibase);
        const float4 spB = *(const float4*)(scale_sp   + oB * IN_DIM + ibase);
        const float4 mkB = *(const float4*)(mask       + oB * IN_DIM + ibase);
        msbB = make_float4(mkB.x*sbB.x, mkB.y*sbB.y, mkB.z*sbB.z, mkB.w*sbB.w);
        mssB = make_float4(mkB.x*spB.x, mkB.y*spB.y, mkB.z*spB.z, mkB.w*spB.w);
    }

    __syncthreads();

    #pragma unroll
    for (int b = 0; b < TILE_B; b++) {
        const int bg = b0 + b;
        float4 spa = make_float4(0.f,0.f,0.f,0.f);
        float4 spb = make_float4(0.f,0.f,0.f,0.f);
        #pragma unroll
        for (int j = 0; j < NB; j++) {
            const float4 bv = Bsh[b][j][L];
            spa.x = fmaf(cfa[0][j], bv.x, spa.x);
            spa.y = fmaf(cfa[1][j], bv.y, spa.y);
            spa.z = fmaf(cfa[2][j], bv.z, spa.z);
            spa.w = fmaf(cfa[3][j], bv.w, spa.w);
            spb.x = fmaf(cfb[0][j], bv.x, spb.x);
            spb.y = fmaf(cfb[1][j], bv.y, spb.y);
            spb.z = fmaf(cfb[2][j], bv.z, spb.z);
            spb.w = fmaf(cfb[3][j], bv.w, spb.w);
        }
        const float4 sl = ssh[b][L];
        float4 ya, yb;
        ya.x = fmaf(mssA.x, spa.x, msbA.x * sl.x);
        ya.y = fmaf(mssA.y, spa.y, msbA.y * sl.y);
        ya.z = fmaf(mssA.z, spa.z, msbA.z * sl.z);
        ya.w = fmaf(mssA.w, spa.w, msbA.w * sl.w);
        yb.x = fmaf(mssB.x, spb.x, msbB.x * sl.x);
        yb.y = fmaf(mssB.y, spb.y, msbB.y * sl.y);
        yb.z = fmaf(mssB.z, spb.z, msbB.z * sl.z);
        yb.w = fmaf(mssB.w, spb.w, msbB.w * sl.w);

        const size_t baseA = ((size_t)bg * OUT_DIM + oA) * IN_DIM + 4 * L;
        const size_t baseB = ((size_t)bg * OUT_DIM + oB) * IN_DIM + 4 * L;
        *(float4*)(postacts   + baseA) = ya;
        *(float4*)(postspline + baseA) = spa;
        *(float4*)(postacts   + baseB) = yb;
        *(float4*)(postspline + baseB) = spb;

        float accA = (ya.x + ya.y) + (ya.z + ya.w);
        float accB = (yb.x + yb.y) + (yb.z + yb.w);
        #pragma unroll
        for (int off = 16; off > 0; off >>= 1) {
            accA += __shfl_down_sync(0xffffffffu, accA, off);
            accB += __shfl_down_sync(0xffffffffu, accB, off);
        }
        if (L == 0) {
            y_out[bg * OUT_DIM + oA] = accA;
            y_out[bg * OUT_DIM + oB] = accB;
        }
    }
}

// ---------------------------------------------------------------------------
extern "C" void kernel_launch(void* const* d_in, const int* in_sizes, int n_in,
                              void* d_out, int out_size)
{
    const float* x          = (const float*)d_in[0];
    const float* grid       = (const float*)d_in[1];
    const float* coef       = (const float*)d_in[2];
    const float* scale_base = (const float*)d_in[3];
    const float* scale_sp   = (const float*)d_in[4];
    const float* mask       = (const float*)d_in[5];
    float* out = (float*)d_out;

    kan_basis_kernel<<<(BATCHSZ * IN_DIM + 255) / 256, 256>>>(x, grid);

    // 1024 main blocks + 512 copy blocks, interleaved 2:1.
    kan_fused_kernel<<<1536, NTHREADS>>>(x, coef, scale_base, scale_sp, mask, out);
}

// round 6
// speedup vs baseline: 1.0121x; 1.0121x over previous
#include <cuda_runtime.h>
#include <cuda_fp16.h>
#include <math.h>

// KANLayer: IN=128, OUT=128, SIZE=16384, BATCH=1024, NUM=5, K=3 -> 8 basis fns.
// L1-wavefront-minimized design:
//   K1: basis once per (b,i), packed fp16, interleaved layout
//       g_basis_h[b][r][L][j]  (i = 4L + r)  -> one contiguous LDG.128 per
//       (warp, b, r) in K2. silu -> g_silu (fp32).
//   K2: no smem, no staging. Warp computes 2 outputs (o, o+8) per basis read;
//       lane owns i-quad 4L..4L+3 -> all 6 stores are STG.128.

#define IN_DIM   128
#define OUT_DIM  128
#define BATCHSZ  1024
#define NB       8
#define NKNOT    12
#define TILE_B   8
#define NTHREADS 256

__device__ __align__(16) __half g_basis_h[BATCHSZ * 4 * 32 * NB]; // [b][r][L][j]
__device__ float g_silu[BATCHSZ * IN_DIM];

// ---------------------------------------------------------------------------
// Kernel 1: Cox-de-Boor basis (fp32 math, fp16 output), 2 batch rows / block.
// Warp layout: wid -> (b_local = wid>>2, r = wid&3), lane L -> i = 4L + r.
// ---------------------------------------------------------------------------
__global__ __launch_bounds__(256)
void kan_basis_kernel(const float* __restrict__ x,
                      const float* __restrict__ grid)
{
    __shared__ float sx [2][IN_DIM];
    __shared__ float ssi[2][IN_DIM];

    const int tid = threadIdx.x;
    const int b0  = blockIdx.x * 2;

    // coalesced x staging
    sx[tid >> 7][tid & 127] = x[b0 * IN_DIM + tid];
    __syncthreads();

    const int wid = tid >> 5;
    const int L   = tid & 31;
    const int bl  = wid >> 2;      // 0..1
    const int r   = wid & 3;       // 0..3
    const int i   = 4 * L + r;
    const float xv = sx[bl][i];

    float t[NKNOT];
    t[3] = grid[i * 6 + 0];
    t[4] = grid[i * 6 + 1];
    t[5] = grid[i * 6 + 2];
    t[6] = grid[i * 6 + 3];
    t[7] = grid[i * 6 + 4];
    t[8] = grid[i * 6 + 5];
    const float h = (t[8] - t[3]) * 0.2f;
    t[2] = t[3] - h;  t[1] = t[2] - h;  t[0]  = t[1]  - h;
    t[9] = t[8] + h;  t[10] = t[9] + h; t[11] = t[10] + h;

    float Bv[NKNOT - 1];
    #pragma unroll
    for (int m = 0; m < NKNOT - 1; m++)
        Bv[m] = (xv >= t[m] && xv < t[m + 1]) ? 1.0f : 0.0f;

    #pragma unroll
    for (int pd = 1; pd <= 3; pd++) {
        #pragma unroll
        for (int m = 0; m < NKNOT - 2; m++) {
            if (m < (NKNOT - 1) - pd) {
                const float a = __fdividef(xv - t[m],          t[m + pd] - t[m]);
                const float c = __fdividef(t[m + pd + 1] - xv, t[m + pd + 1] - t[m + 1]);
                Bv[m] = a * Bv[m] + c * Bv[m + 1];
            }
        }
    }

    // pack 8 basis values -> 4 half2 -> one coalesced 16B store
    __half2 hp[4];
    hp[0] = __floats2half2_rn(Bv[0], Bv[1]);
    hp[1] = __floats2half2_rn(Bv[2], Bv[3]);
    hp[2] = __floats2half2_rn(Bv[4], Bv[5]);
    hp[3] = __floats2half2_rn(Bv[6], Bv[7]);
    ((uint4*)g_basis_h)[((b0 + bl) * 4 + r) * 32 + L] = *(const uint4*)hp;

    // silu via smem for coalesced store
    ssi[bl][i] = __fdividef(xv, 1.0f + __expf(-xv));
    __syncthreads();
    g_silu[b0 * IN_DIM + tid] = ssi[tid >> 7][tid & 127];
}

// ---------------------------------------------------------------------------
// Kernel 2: main streaming compute. No shared memory.
// 8 warps; warp w -> outputs (o0+w, o0+8+w); lane L -> i = 4L..4L+3.
// ---------------------------------------------------------------------------
__global__ __launch_bounds__(NTHREADS, 2)
void kan_main_kernel(const float* __restrict__ x,
                     const float* __restrict__ coef,
                     const float* __restrict__ scale_base,
                     const float* __restrict__ scale_sp,
                     const float* __restrict__ mask,
                     float* __restrict__ out)
{
    const int b0   = blockIdx.x * TILE_B;
    const int warp = threadIdx.x >> 5;
    const int L    = threadIdx.x & 31;
    const int oA   = blockIdx.y * 16 + warp;
    const int oB   = oA + 8;

    // ---- per-thread constants for both o's ----
    float cfa[4][NB], cfb[4][NB];
    float4 msbA, mssA, msbB, mssB;
    {
        const int ibase = 4 * L;
        #pragma unroll
        for (int q = 0; q < 4; q++) {
            const int sA = oA * IN_DIM + ibase + q;
            const int sB = oB * IN_DIM + ibase + q;
            float4 a0 = *(const float4*)(coef + sA * NB);
            float4 a1 = *(const float4*)(coef + sA * NB + 4);
            cfa[q][0]=a0.x; cfa[q][1]=a0.y; cfa[q][2]=a0.z; cfa[q][3]=a0.w;
            cfa[q][4]=a1.x; cfa[q][5]=a1.y; cfa[q][6]=a1.z; cfa[q][7]=a1.w;
            float4 c0 = *(const float4*)(coef + sB * NB);
            float4 c1 = *(const float4*)(coef + sB * NB + 4);
            cfb[q][0]=c0.x; cfb[q][1]=c0.y; cfb[q][2]=c0.z; cfb[q][3]=c0.w;
            cfb[q][4]=c1.x; cfb[q][5]=c1.y; cfb[q][6]=c1.z; cfb[q][7]=c1.w;
        }
        const float4 sbA = *(const float4*)(scale_base + oA * IN_DIM + ibase);
        const float4 spA = *(const float4*)(scale_sp   + oA * IN_DIM + ibase);
        const float4 mkA = *(const float4*)(mask       + oA * IN_DIM + ibase);
        msbA = make_float4(mkA.x*sbA.x, mkA.y*sbA.y, mkA.z*sbA.z, mkA.w*sbA.w);
        mssA = make_float4(mkA.x*spA.x, mkA.y*spA.y, mkA.z*spA.z, mkA.w*spA.w);
        const float4 sbB = *(const float4*)(scale_base + oB * IN_DIM + ibase);
        const float4 spB = *(const float4*)(scale_sp   + oB * IN_DIM + ibase);
        const float4 mkB = *(const float4*)(mask       + oB * IN_DIM + ibase);
        msbB = make_float4(mkB.x*sbB.x, mkB.y*sbB.y, mkB.z*sbB.z, mkB.w*sbB.w);
        mssB = make_float4(mkB.x*spB.x, mkB.y*spB.y, mkB.z*spB.z, mkB.w*spB.w);
    }

    const size_t P = (size_t)BATCHSZ * OUT_DIM * IN_DIM;
    float* y_out      = out;
    float* preacts    = out + (size_t)BATCHSZ * OUT_DIM;
    float* postacts   = preacts + P;
    float* postspline = postacts + P;

    const uint4* bp = (const uint4*)g_basis_h;

    #pragma unroll 2
    for (int b = 0; b < TILE_B; b++) {
        const int bg = b0 + b;
        const int ib = bg * 128 + L;   // uint4 index of [bg][0][L]

        float spa[4], spb[4];
        #pragma unroll
        for (int r = 0; r < 4; r++) {
            const uint4 hv = __ldg(&bp[ib + r * 32]);
            const __half2* hh = (const __half2*)&hv;
            const float2 f0 = __half22float2(hh[0]);
            const float2 f1 = __half22float2(hh[1]);
            const float2 f2 = __half22float2(hh[2]);
            const float2 f3 = __half22float2(hh[3]);
            float sA, sB;
            sA = cfa[r][0] * f0.x;              sB = cfb[r][0] * f0.x;
            sA = fmaf(cfa[r][1], f0.y, sA);     sB = fmaf(cfb[r][1], f0.y, sB);
            sA = fmaf(cfa[r][2], f1.x, sA);     sB = fmaf(cfb[r][2], f1.x, sB);
            sA = fmaf(cfa[r][3], f1.y, sA);     sB = fmaf(cfb[r][3], f1.y, sB);
            sA = fmaf(cfa[r][4], f2.x, sA);     sB = fmaf(cfb[r][4], f2.x, sB);
            sA = fmaf(cfa[r][5], f2.y, sA);     sB = fmaf(cfb[r][5], f2.y, sB);
            sA = fmaf(cfa[r][6], f3.x, sA);     sB = fmaf(cfb[r][6], f3.x, sB);
            sA = fmaf(cfa[r][7], f3.y, sA);     sB = fmaf(cfb[r][7], f3.y, sB);
            spa[r] = sA; spb[r] = sB;
        }

        const float4 xv = __ldg((const float4*)(x + bg * IN_DIM) + L);
        const float4 sl = __ldg((const float4*)(g_silu + bg * IN_DIM) + L);

        float4 ya, yb;
        ya.x = fmaf(mssA.x, spa[0], msbA.x * sl.x);
        ya.y = fmaf(mssA.y, spa[1], msbA.y * sl.y);
        ya.z = fmaf(mssA.z, spa[2], msbA.z * sl.z);
        ya.w = fmaf(mssA.w, spa[3], msbA.w * sl.w);
        yb.x = fmaf(mssB.x, spb[0], msbB.x * sl.x);
        yb.y = fmaf(mssB.y, spb[1], msbB.y * sl.y);
        yb.z = fmaf(mssB.z, spb[2], msbB.z * sl.z);
        yb.w = fmaf(mssB.w, spb[3], msbB.w * sl.w);

        const size_t baseA = ((size_t)bg * OUT_DIM + oA) * IN_DIM + 4 * L;
        const size_t baseB = ((size_t)bg * OUT_DIM + oB) * IN_DIM + 4 * L;
        const float4 sva = make_float4(spa[0], spa[1], spa[2], spa[3]);
        const float4 svb = make_float4(spb[0], spb[1], spb[2], spb[3]);
        __stcs((float4*)(preacts    + baseA), xv);
        __stcs((float4*)(postacts   + baseA), ya);
        __stcs((float4*)(postspline + baseA), sva);
        __stcs((float4*)(preacts    + baseB), xv);
        __stcs((float4*)(postacts   + baseB), yb);
        __stcs((float4*)(postspline + baseB), svb);

        float accA = (ya.x + ya.y) + (ya.z + ya.w);
        float accB = (yb.x + yb.y) + (yb.z + yb.w);
        #pragma unroll
        for (int off = 16; off > 0; off >>= 1) {
            accA += __shfl_down_sync(0xffffffffu, accA, off);
            accB += __shfl_down_sync(0xffffffffu, accB, off);
        }
        if (L == 0) {
            y_out[bg * OUT_DIM + oA] = accA;
            y_out[bg * OUT_DIM + oB] = accB;
        }
    }
}

// ---------------------------------------------------------------------------
extern "C" void kernel_launch(void* const* d_in, const int* in_sizes, int n_in,
                              void* d_out, int out_size)
{
    const float* x          = (const float*)d_in[0];
    const float* grid       = (const float*)d_in[1];
    const float* coef       = (const float*)d_in[2];
    const float* scale_base = (const float*)d_in[3];
    const float* scale_sp   = (const float*)d_in[4];
    const float* mask       = (const float*)d_in[5];
    float* out = (float*)d_out;

    kan_basis_kernel<<<BATCHSZ / 2, 256>>>(x, grid);

    dim3 g(BATCHSZ / TILE_B, OUT_DIM / 16);
    kan_main_kernel<<<g, NTHREADS>>>(x, coef, scale_base, scale_sp, mask, out);
}

// round 7
// speedup vs baseline: 1.0930x; 1.0799x over previous
#include <cuda_runtime.h>
#include <cuda_fp16.h>
#include <math.h>

// KANLayer: IN=128, OUT=128, SIZE=16384, BATCH=1024, NUM=5, K=3 -> 8 basis fns.
// Model: main kernel is bound by L1 shared/store DATA-PATH cycles (bytes moved).
// R7: fp16 basis in smem ([b][j][i] halves -> conflict-free LDS.64 per j),
//     halving basis bytes vs R4. Everything else = R4 (best known).

#define IN_DIM   128
#define OUT_DIM  128
#define BATCHSZ  1024
#define NB       8
#define NKNOT    12
#define TILE_B   8
#define NTHREADS 256

__device__ __align__(16) __half g_basis_h[BATCHSZ * NB * IN_DIM];  // [b][j][i]
__device__ float g_silu[BATCHSZ * IN_DIM];

// ---------------------------------------------------------------------------
// Kernel 1: basis per (b,i), fp32 math (fast divides), fp16 out via smem
// transpose for coalesced stores. Block = 2 batch rows (256 threads).
// ---------------------------------------------------------------------------
__global__ __launch_bounds__(256)
void kan_basis_kernel(const float* __restrict__ x,
                      const float* __restrict__ grid)
{
    __shared__ __half sh[2 * NB * IN_DIM];   // [bl][j][i]

    const int tid = threadIdx.x;
    const int b0  = blockIdx.x * 2;
    const int bl  = tid >> 7;
    const int i   = tid & 127;

    const float xv = x[b0 * IN_DIM + tid];   // coalesced; this thread's value

    float t[NKNOT];
    t[3] = grid[i * 6 + 0];
    t[4] = grid[i * 6 + 1];
    t[5] = grid[i * 6 + 2];
    t[6] = grid[i * 6 + 3];
    t[7] = grid[i * 6 + 4];
    t[8] = grid[i * 6 + 5];
    const float h = (t[8] - t[3]) * 0.2f;
    t[2] = t[3] - h;  t[1] = t[2] - h;  t[0]  = t[1]  - h;
    t[9] = t[8] + h;  t[10] = t[9] + h; t[11] = t[10] + h;

    float Bv[NKNOT - 1];
    #pragma unroll
    for (int m = 0; m < NKNOT - 1; m++)
        Bv[m] = (xv >= t[m] && xv < t[m + 1]) ? 1.0f : 0.0f;

    #pragma unroll
    for (int pd = 1; pd <= 3; pd++) {
        #pragma unroll
        for (int m = 0; m < NKNOT - 2; m++) {
            if (m < (NKNOT - 1) - pd) {
                const float a = __fdividef(xv - t[m],          t[m + pd] - t[m]);
                const float c = __fdividef(t[m + pd + 1] - xv, t[m + pd + 1] - t[m + 1]);
                Bv[m] = a * Bv[m] + c * Bv[m + 1];
            }
        }
    }

    #pragma unroll
    for (int j = 0; j < NB; j++)
        sh[(bl * NB + j) * IN_DIM + i] = __float2half_rn(Bv[j]);

    g_silu[b0 * IN_DIM + tid] = __fdividef(xv, 1.0f + __expf(-xv));

    __syncthreads();
    // coalesced copy out: 2*8*128 halves = 4KB = 256 uint4
    ((uint4*)(g_basis_h + b0 * NB * IN_DIM))[tid] = ((const uint4*)sh)[tid];
}

// ---------------------------------------------------------------------------
// Kernel 2: main streaming compute (R4 structure, fp16 basis).
// 8 warps; warp w -> outputs (o0+w, o0+8+w); lane L -> i = 4L..4L+3.
// ---------------------------------------------------------------------------
__global__ __launch_bounds__(NTHREADS, 2)
void kan_main_kernel(const float* __restrict__ x,
                     const float* __restrict__ coef,
                     const float* __restrict__ scale_base,
                     const float* __restrict__ scale_sp,
                     const float* __restrict__ mask,
                     float* __restrict__ out)
{
    __shared__ __half  Bsh[TILE_B * NB * IN_DIM];   // [b][j][i]  16KB
    __shared__ float4  xsh[TILE_B][IN_DIM / 4];     // 4KB
    __shared__ float4  ssh[TILE_B][IN_DIM / 4];     // 4KB

    const int b0   = blockIdx.x * TILE_B;
    const int warp = threadIdx.x >> 5;
    const int L    = threadIdx.x & 31;
    const int oA   = blockIdx.y * 16 + warp;
    const int oB   = oA + 8;

    // ---- stage basis (fp16) / x / silu tiles ----
    {
        const uint4* gb = (const uint4*)(g_basis_h + b0 * NB * IN_DIM);
        uint4* db = (uint4*)Bsh;
        #pragma unroll
        for (int idx = threadIdx.x; idx < TILE_B * NB * IN_DIM / 8; idx += NTHREADS)
            db[idx] = gb[idx];
        const float4* gx = (const float4*)(x + b0 * IN_DIM);
        const float4* gs = (const float4*)(g_silu + b0 * IN_DIM);
        float4* dx = &xsh[0][0];
        float4* ds = &ssh[0][0];
        #pragma unroll
        for (int idx = threadIdx.x; idx < TILE_B * (IN_DIM / 4); idx += NTHREADS) {
            dx[idx] = gx[idx];
            ds[idx] = gs[idx];
        }
    }

    // ---- per-thread constants for both o's ----
    float cfa[4][NB], cfb[4][NB];
    float4 msbA, mssA, msbB, mssB;
    {
        const int ibase = 4 * L;
        #pragma unroll
        for (int q = 0; q < 4; q++) {
            const int sA = oA * IN_DIM + ibase + q;
            const int sB = oB * IN_DIM + ibase + q;
            float4 a0 = *(const float4*)(coef + sA * NB);
            float4 a1 = *(const float4*)(coef + sA * NB + 4);
            cfa[q][0]=a0.x; cfa[q][1]=a0.y; cfa[q][2]=a0.z; cfa[q][3]=a0.w;
            cfa[q][4]=a1.x; cfa[q][5]=a1.y; cfa[q][6]=a1.z; cfa[q][7]=a1.w;
            float4 c0 = *(const float4*)(coef + sB * NB);
            float4 c1 = *(const float4*)(coef + sB * NB + 4);
            cfb[q][0]=c0.x; cfb[q][1]=c0.y; cfb[q][2]=c0.z; cfb[q][3]=c0.w;
            cfb[q][4]=c1.x; cfb[q][5]=c1.y; cfb[q][6]=c1.z; cfb[q][7]=c1.w;
        }
        const float4 sbA = *(const float4*)(scale_base + oA * IN_DIM + ibase);
        const float4 spA = *(const float4*)(scale_sp   + oA * IN_DIM + ibase);
        const float4 mkA = *(const float4*)(mask       + oA * IN_DIM + ibase);
        msbA = make_float4(mkA.x*sbA.x, mkA.y*sbA.y, mkA.z*sbA.z, mkA.w*sbA.w);
        mssA = make_float4(mkA.x*spA.x, mkA.y*spA.y, mkA.z*spA.z, mkA.w*spA.w);
        const float4 sbB = *(const float4*)(scale_base + oB * IN_DIM + ibase);
        const float4 spB = *(const float4*)(scale_sp   + oB * IN_DIM + ibase);
        const float4 mkB = *(const float4*)(mask       + oB * IN_DIM + ibase);
        msbB = make_float4(mkB.x*sbB.x, mkB.y*sbB.y, mkB.z*sbB.z, mkB.w*sbB.w);
        mssB = make_float4(mkB.x*spB.x, mkB.y*spB.y, mkB.z*spB.z, mkB.w*spB.w);
    }

    __syncthreads();

    const size_t P = (size_t)BATCHSZ * OUT_DIM * IN_DIM;
    float* y_out      = out;
    float* preacts    = out + (size_t)BATCHSZ * OUT_DIM;
    float* postacts   = preacts + P;
    float* postspline = postacts + P;

    #pragma unroll
    for (int b = 0; b < TILE_B; b++) {
        const int bg = b0 + b;
        float spa[4] = {0.f, 0.f, 0.f, 0.f};
        float spb[4] = {0.f, 0.f, 0.f, 0.f};
        #pragma unroll
        for (int j = 0; j < NB; j++) {
            // lane's i-quad (i = 4L..4L+3) for basis fn j: one LDS.64
            const uint2 hv = *((const uint2*)(Bsh + (b * NB + j) * IN_DIM) + L);
            const float2 f01 = __half22float2(*(const __half2*)&hv.x);
            const float2 f23 = __half22float2(*(const __half2*)&hv.y);
            spa[0] = fmaf(cfa[0][j], f01.x, spa[0]);
            spa[1] = fmaf(cfa[1][j], f01.y, spa[1]);
            spa[2] = fmaf(cfa[2][j], f23.x, spa[2]);
            spa[3] = fmaf(cfa[3][j], f23.y, spa[3]);
            spb[0] = fmaf(cfb[0][j], f01.x, spb[0]);
            spb[1] = fmaf(cfb[1][j], f01.y, spb[1]);
            spb[2] = fmaf(cfb[2][j], f23.x, spb[2]);
            spb[3] = fmaf(cfb[3][j], f23.y, spb[3]);
        }
        const float4 xv = xsh[b][L];
        const float4 sl = ssh[b][L];
        float4 ya, yb;
        ya.x = fmaf(mssA.x, spa[0], msbA.x * sl.x);
        ya.y = fmaf(mssA.y, spa[1], msbA.y * sl.y);
        ya.z = fmaf(mssA.z, spa[2], msbA.z * sl.z);
        ya.w = fmaf(mssA.w, spa[3], msbA.w * sl.w);
        yb.x = fmaf(mssB.x, spb[0], msbB.x * sl.x);
        yb.y = fmaf(mssB.y, spb[1], msbB.y * sl.y);
        yb.z = fmaf(mssB.z, spb[2], msbB.z * sl.z);
        yb.w = fmaf(mssB.w, spb[3], msbB.w * sl.w);

        const size_t baseA = ((size_t)bg * OUT_DIM + oA) * IN_DIM + 4 * L;
        const size_t baseB = ((size_t)bg * OUT_DIM + oB) * IN_DIM + 4 * L;
        const float4 sva = make_float4(spa[0], spa[1], spa[2], spa[3]);
        const float4 svb = make_float4(spb[0], spb[1], spb[2], spb[3]);
        *(float4*)(preacts    + baseA) = xv;
        *(float4*)(postacts   + baseA) = ya;
        *(float4*)(postspline + baseA) = sva;
        *(float4*)(preacts    + baseB) = xv;
        *(float4*)(postacts   + baseB) = yb;
        *(float4*)(postspline + baseB) = svb;

        float accA = (ya.x + ya.y) + (ya.z + ya.w);
        float accB = (yb.x + yb.y) + (yb.z + yb.w);
        #pragma unroll
        for (int off = 16; off > 0; off >>= 1) {
            accA += __shfl_down_sync(0xffffffffu, accA, off);
            accB += __shfl_down_sync(0xffffffffu, accB, off);
        }
        if (L == 0) {
            y_out[bg * OUT_DIM + oA] = accA;
            y_out[bg * OUT_DIM + oB] = accB;
        }
    }
}

// ---------------------------------------------------------------------------
extern "C" void kernel_launch(void* const* d_in, const int* in_sizes, int n_in,
                              void* d_out, int out_size)
{
    const float* x          = (const float*)d_in[0];
    const float* grid       = (const float*)d_in[1];
    const float* coef       = (const float*)d_in[2];
    const float* scale_base = (const float*)d_in[3];
    const float* scale_sp   = (const float*)d_in[4];
    const float* mask       = (const float*)d_in[5];
    float* out = (float*)d_out;

    kan_basis_kernel<<<BATCHSZ / 2, 256>>>(x, grid);

    dim3 g(BATCHSZ / TILE_B, OUT_DIM / 16);
    kan_main_kernel<<<g, NTHREADS>>>(x, coef, scale_base, scale_sp, mask, out);
}

// round 8
// speedup vs baseline: 1.1392x; 1.0423x over previous
#include <cuda_runtime.h>
#include <cuda_fp16.h>
#include <math.h>

// KANLayer: IN=128, OUT=128, SIZE=16384, BATCH=1024, NUM=5, K=3 -> 8 basis fns.
// R8: basis layout [b][i][j] fp16 + SW128 swizzle in smem -> lane reads all 8
//     basis values of one i as ONE LDS.128 (4 per warp-iter, was 8 LDS.64).
//     K1 stores one uint4 per (b,i), naturally coalesced. __stcs outputs.

#define IN_DIM   128
#define OUT_DIM  128
#define BATCHSZ  1024
#define NB       8
#define NKNOT    12
#define TILE_B   8
#define NTHREADS 256

#define SW128(off) ((off) ^ (((off) >> 3) & 0x70))

__device__ __align__(16) __half g_basis_h[BATCHSZ * IN_DIM * NB];  // [b][i][j]
__device__ float g_silu[BATCHSZ * IN_DIM];

// ---------------------------------------------------------------------------
// Kernel 1: basis per (b,i); one uint4 (8 fp16) store per thread, coalesced.
// ---------------------------------------------------------------------------
__global__ __launch_bounds__(256)
void kan_basis_kernel(const float* __restrict__ x,
                      const float* __restrict__ grid)
{
    const int p = blockIdx.x * 256 + threadIdx.x;   // (b,i) pair
    if (p >= BATCHSZ * IN_DIM) return;
    const int i  = p & (IN_DIM - 1);
    const float xv = x[p];

    float t[NKNOT];
    t[3] = grid[i * 6 + 0];
    t[4] = grid[i * 6 + 1];
    t[5] = grid[i * 6 + 2];
    t[6] = grid[i * 6 + 3];
    t[7] = grid[i * 6 + 4];
    t[8] = grid[i * 6 + 5];
    const float h = (t[8] - t[3]) * 0.2f;
    t[2] = t[3] - h;  t[1] = t[2] - h;  t[0]  = t[1]  - h;
    t[9] = t[8] + h;  t[10] = t[9] + h; t[11] = t[10] + h;

    float Bv[NKNOT - 1];
    #pragma unroll
    for (int m = 0; m < NKNOT - 1; m++)
        Bv[m] = (xv >= t[m] && xv < t[m + 1]) ? 1.0f : 0.0f;

    #pragma unroll
    for (int pd = 1; pd <= 3; pd++) {
        #pragma unroll
        for (int m = 0; m < NKNOT - 2; m++) {
            if (m < (NKNOT - 1) - pd) {
                const float a = __fdividef(xv - t[m],          t[m + pd] - t[m]);
                const float c = __fdividef(t[m + pd + 1] - xv, t[m + pd + 1] - t[m + 1]);
                Bv[m] = a * Bv[m] + c * Bv[m + 1];
            }
        }
    }

    __half2 hp[4];
    hp[0] = __floats2half2_rn(Bv[0], Bv[1]);
    hp[1] = __floats2half2_rn(Bv[2], Bv[3]);
    hp[2] = __floats2half2_rn(Bv[4], Bv[5]);
    hp[3] = __floats2half2_rn(Bv[6], Bv[7]);
    ((uint4*)g_basis_h)[p] = *(const uint4*)hp;

    g_silu[p] = __fdividef(xv, 1.0f + __expf(-xv));
}

// ---------------------------------------------------------------------------
// Kernel 2: main streaming compute. Basis tile in smem, [b][i][j] + SW128.
// 8 warps; warp w -> outputs (o0+w, o0+8+w); lane L -> i = 4L..4L+3.
// ---------------------------------------------------------------------------
__global__ __launch_bounds__(NTHREADS, 2)
void kan_main_kernel(const float* __restrict__ x,
                     const float* __restrict__ coef,
                     const float* __restrict__ scale_base,
                     const float* __restrict__ scale_sp,
                     const float* __restrict__ mask,
                     float* __restrict__ out)
{
    __shared__ __align__(1024) char Bsh[TILE_B * IN_DIM * NB * 2]; // 16KB swizzled
    __shared__ float4 xsh[TILE_B][IN_DIM / 4];
    __shared__ float4 ssh[TILE_B][IN_DIM / 4];

    const int b0   = blockIdx.x * TILE_B;
    const int warp = threadIdx.x >> 5;
    const int L    = threadIdx.x & 31;
    const int oA   = blockIdx.y * 16 + warp;
    const int oB   = oA + 8;

    // ---- stage basis (swizzled write) / x / silu ----
    {
        const uint4* gb = (const uint4*)(g_basis_h + b0 * IN_DIM * NB);
        #pragma unroll
        for (int idx = threadIdx.x; idx < TILE_B * IN_DIM; idx += NTHREADS) {
            const int off = idx * 16;
            *(uint4*)(Bsh + SW128(off)) = gb[idx];
        }
        const float4* gx = (const float4*)(x + b0 * IN_DIM);
        const float4* gs = (const float4*)(g_silu + b0 * IN_DIM);
        float4* dx = &xsh[0][0];
        float4* ds = &ssh[0][0];
        #pragma unroll
        for (int idx = threadIdx.x; idx < TILE_B * (IN_DIM / 4); idx += NTHREADS) {
            dx[idx] = gx[idx];
            ds[idx] = gs[idx];
        }
    }

    // ---- per-thread constants for both o's ----
    float cfa[4][NB], cfb[4][NB];
    float4 msbA, mssA, msbB, mssB;
    {
        const int ibase = 4 * L;
        #pragma unroll
        for (int q = 0; q < 4; q++) {
            const int sA = oA * IN_DIM + ibase + q;
            const int sB = oB * IN_DIM + ibase + q;
            float4 a0 = *(const float4*)(coef + sA * NB);
            float4 a1 = *(const float4*)(coef + sA * NB + 4);
            cfa[q][0]=a0.x; cfa[q][1]=a0.y; cfa[q][2]=a0.z; cfa[q][3]=a0.w;
            cfa[q][4]=a1.x; cfa[q][5]=a1.y; cfa[q][6]=a1.z; cfa[q][7]=a1.w;
            float4 c0 = *(const float4*)(coef + sB * NB);
            float4 c1 = *(const float4*)(coef + sB * NB + 4);
            cfb[q][0]=c0.x; cfb[q][1]=c0.y; cfb[q][2]=c0.z; cfb[q][3]=c0.w;
            cfb[q][4]=c1.x; cfb[q][5]=c1.y; cfb[q][6]=c1.z; cfb[q][7]=c1.w;
        }
        const float4 sbA = *(const float4*)(scale_base + oA * IN_DIM + ibase);
        const float4 spA = *(const float4*)(scale_sp   + oA * IN_DIM + ibase);
        const float4 mkA = *(const float4*)(mask       + oA * IN_DIM + ibase);
        msbA = make_float4(mkA.x*sbA.x, mkA.y*sbA.y, mkA.z*sbA.z, mkA.w*sbA.w);
        mssA = make_float4(mkA.x*spA.x, mkA.y*spA.y, mkA.z*spA.z, mkA.w*spA.w);
        const float4 sbB = *(const float4*)(scale_base + oB * IN_DIM + ibase);
        const float4 spB = *(const float4*)(scale_sp   + oB * IN_DIM + ibase);
        const float4 mkB = *(const float4*)(mask       + oB * IN_DIM + ibase);
        msbB = make_float4(mkB.x*sbB.x, mkB.y*sbB.y, mkB.z*sbB.z, mkB.w*sbB.w);
        mssB = make_float4(mkB.x*spB.x, mkB.y*spB.y, mkB.z*spB.z, mkB.w*spB.w);
    }

    __syncthreads();

    const size_t P = (size_t)BATCHSZ * OUT_DIM * IN_DIM;
    float* y_out      = out;
    float* preacts    = out + (size_t)BATCHSZ * OUT_DIM;
    float* postacts   = preacts + P;
    float* postspline = postacts + P;

    #pragma unroll
    for (int b = 0; b < TILE_B; b++) {
        const int bg = b0 + b;

        // prefetch lane's 4 basis vectors (one LDS.128 per i)
        uint4 hv[4];
        #pragma unroll
        for (int q = 0; q < 4; q++) {
            const int off = (b * IN_DIM + 4 * L + q) * 16;
            hv[q] = *(const uint4*)(Bsh + SW128(off));
        }

        float spa[4], spb[4];
        #pragma unroll
        for (int q = 0; q < 4; q++) {
            const __half2* hh = (const __half2*)&hv[q];
            const float2 f0 = __half22float2(hh[0]);
            const float2 f1 = __half22float2(hh[1]);
            const float2 f2 = __half22float2(hh[2]);
            const float2 f3 = __half22float2(hh[3]);
            float sA, sB;
            sA = cfa[q][0] * f0.x;            sB = cfb[q][0] * f0.x;
            sA = fmaf(cfa[q][1], f0.y, sA);   sB = fmaf(cfb[q][1], f0.y, sB);
            sA = fmaf(cfa[q][2], f1.x, sA);   sB = fmaf(cfb[q][2], f1.x, sB);
            sA = fmaf(cfa[q][3], f1.y, sA);   sB = fmaf(cfb[q][3], f1.y, sB);
            sA = fmaf(cfa[q][4], f2.x, sA);   sB = fmaf(cfb[q][4], f2.x, sB);
            sA = fmaf(cfa[q][5], f2.y, sA);   sB = fmaf(cfb[q][5], f2.y, sB);
            sA = fmaf(cfa[q][6], f3.x, sA);   sB = fmaf(cfb[q][6], f3.x, sB);
            sA = fmaf(cfa[q][7], f3.y, sA);   sB = fmaf(cfb[q][7], f3.y, sB);
            spa[q] = sA; spb[q] = sB;
        }

        const float4 xv = xsh[b][L];
        const float4 sl = ssh[b][L];
        float4 ya, yb;
        ya.x = fmaf(mssA.x, spa[0], msbA.x * sl.x);
        ya.y = fmaf(mssA.y, spa[1], msbA.y * sl.y);
        ya.z = fmaf(mssA.z, spa[2], msbA.z * sl.z);
        ya.w = fmaf(mssA.w, spa[3], msbA.w * sl.w);
        yb.x = fmaf(mssB.x, spb[0], msbB.x * sl.x);
        yb.y = fmaf(mssB.y, spb[1], msbB.y * sl.y);
        yb.z = fmaf(mssB.z, spb[2], msbB.z * sl.z);
        yb.w = fmaf(mssB.w, spb[3], msbB.w * sl.w);

        const size_t baseA = ((size_t)bg * OUT_DIM + oA) * IN_DIM + 4 * L;
        const size_t baseB = ((size_t)bg * OUT_DIM + oB) * IN_DIM + 4 * L;
        const float4 sva = make_float4(spa[0], spa[1], spa[2], spa[3]);
        const float4 svb = make_float4(spb[0], spb[1], spb[2], spb[3]);
        __stcs((float4*)(preacts    + baseA), xv);
        __stcs((float4*)(postacts   + baseA), ya);
        __stcs((float4*)(postspline + baseA), sva);
        __stcs((float4*)(preacts    + baseB), xv);
        __stcs((float4*)(postacts   + baseB), yb);
        __stcs((float4*)(postspline + baseB), svb);

        float accA = (ya.x + ya.y) + (ya.z + ya.w);
        float accB = (yb.x + yb.y) + (yb.z + yb.w);
        #pragma unroll
        for (int off = 16; off > 0; off >>= 1) {
            accA += __shfl_down_sync(0xffffffffu, accA, off);
            accB += __shfl_down_sync(0xffffffffu, accB, off);
        }
        if (L == 0) {
            y_out[bg * OUT_DIM + oA] = accA;
            y_out[bg * OUT_DIM + oB] = accB;
        }
    }
}

// ---------------------------------------------------------------------------
extern "C" void kernel_launch(void* const* d_in, const int* in_sizes, int n_in,
                              void* d_out, int out_size)
{
    const float* x          = (const float*)d_in[0];
    const float* grid       = (const float*)d_in[1];
    const float* coef       = (const float*)d_in[2];
    const float* scale_base = (const float*)d_in[3];
    const float* scale_sp   = (const float*)d_in[4];
    const float* mask       = (const float*)d_in[5];
    float* out = (float*)d_out;

    kan_basis_kernel<<<(BATCHSZ * IN_DIM + 255) / 256, 256>>>(x, grid);

    dim3 g(BATCHSZ / TILE_B, OUT_DIM / 16);
    kan_main_kernel<<<g, NTHREADS>>>(x, coef, scale_base, scale_sp, mask, out);
}

// round 12
// speedup vs baseline: 1.1879x; 1.0427x over previous
#include <cuda_runtime.h>
#include <cuda_fp16.h>
#include <math.h>

// KANLayer: IN=128, OUT=128, SIZE=16384, BATCH=1024, NUM=5, K=3 -> 8 basis fns.
// R12 = R8 + deferred multi-value butterfly reduction for y_out:
//   hold 16 partials (8 b x 2 o) in regs, reduce ALL at block end with
//   16 shuffles total (was 80). No redux.f32 on sm_103 (ptxas-verified).

#define IN_DIM   128
#define OUT_DIM  128
#define BATCHSZ  1024
#define NB       8
#define NKNOT    12
#define TILE_B   8
#define NTHREADS 256

#define SW128(off) ((off) ^ (((off) >> 3) & 0x70))

__device__ __align__(16) __half g_basis_h[BATCHSZ * IN_DIM * NB];  // [b][i][j]
__device__ float g_silu[BATCHSZ * IN_DIM];

// ---------------------------------------------------------------------------
// Kernel 1: basis per (b,i); one uint4 (8 fp16) store per thread, coalesced.
// ---------------------------------------------------------------------------
__global__ __launch_bounds__(256)
void kan_basis_kernel(const float* __restrict__ x,
                      const float* __restrict__ grid)
{
    const int p = blockIdx.x * 256 + threadIdx.x;   // (b,i) pair
    if (p >= BATCHSZ * IN_DIM) return;
    const int i  = p & (IN_DIM - 1);
    const float xv = x[p];

    float t[NKNOT];
    t[3] = grid[i * 6 + 0];
    t[4] = grid[i * 6 + 1];
    t[5] = grid[i * 6 + 2];
    t[6] = grid[i * 6 + 3];
    t[7] = grid[i * 6 + 4];
    t[8] = grid[i * 6 + 5];
    const float h = (t[8] - t[3]) * 0.2f;
    t[2] = t[3] - h;  t[1] = t[2] - h;  t[0]  = t[1]  - h;
    t[9] = t[8] + h;  t[10] = t[9] + h; t[11] = t[10] + h;

    float Bv[NKNOT - 1];
    #pragma unroll
    for (int m = 0; m < NKNOT - 1; m++)
        Bv[m] = (xv >= t[m] && xv < t[m + 1]) ? 1.0f : 0.0f;

    #pragma unroll
    for (int pd = 1; pd <= 3; pd++) {
        #pragma unroll
        for (int m = 0; m < NKNOT - 2; m++) {
            if (m < (NKNOT - 1) - pd) {
                const float a = __fdividef(xv - t[m],          t[m + pd] - t[m]);
                const float c = __fdividef(t[m + pd + 1] - xv, t[m + pd + 1] - t[m + 1]);
                Bv[m] = a * Bv[m] + c * Bv[m + 1];
            }
        }
    }

    __half2 hp[4];
    hp[0] = __floats2half2_rn(Bv[0], Bv[1]);
    hp[1] = __floats2half2_rn(Bv[2], Bv[3]);
    hp[2] = __floats2half2_rn(Bv[4], Bv[5]);
    hp[3] = __floats2half2_rn(Bv[6], Bv[7]);
    ((uint4*)g_basis_h)[p] = *(const uint4*)hp;

    g_silu[p] = __fdividef(xv, 1.0f + __expf(-xv));
}

// ---------------------------------------------------------------------------
// Kernel 2: main streaming compute. Basis tile in smem, [b][i][j] + SW128.
// 8 warps; warp w -> outputs (o0+w, o0+8+w); lane L -> i = 4L..4L+3.
// y_out partials v[2b]=(b,oA), v[2b+1]=(b,oB) reduced once at block end.
// ---------------------------------------------------------------------------
__global__ __launch_bounds__(NTHREADS, 2)
void kan_main_kernel(const float* __restrict__ x,
                     const float* __restrict__ coef,
                     const float* __restrict__ scale_base,
                     const float* __restrict__ scale_sp,
                     const float* __restrict__ mask,
                     float* __restrict__ out)
{
    __shared__ __align__(1024) char Bsh[TILE_B * IN_DIM * NB * 2]; // 16KB swizzled
    __shared__ float4 xsh[TILE_B][IN_DIM / 4];
    __shared__ float4 ssh[TILE_B][IN_DIM / 4];

    const int b0   = blockIdx.x * TILE_B;
    const int warp = threadIdx.x >> 5;
    const int L    = threadIdx.x & 31;
    const int oA   = blockIdx.y * 16 + warp;
    const int oB   = oA + 8;

    // ---- stage basis (swizzled write) / x / silu ----
    {
        const uint4* gb = (const uint4*)(g_basis_h + b0 * IN_DIM * NB);
        #pragma unroll
        for (int idx = threadIdx.x; idx < TILE_B * IN_DIM; idx += NTHREADS) {
            const int off = idx * 16;
            *(uint4*)(Bsh + SW128(off)) = gb[idx];
        }
        const float4* gx = (const float4*)(x + b0 * IN_DIM);
        const float4* gs = (const float4*)(g_silu + b0 * IN_DIM);
        float4* dx = &xsh[0][0];
        float4* ds = &ssh[0][0];
        #pragma unroll
        for (int idx = threadIdx.x; idx < TILE_B * (IN_DIM / 4); idx += NTHREADS) {
            dx[idx] = gx[idx];
            ds[idx] = gs[idx];
        }
    }

    // ---- per-thread constants for both o's ----
    float cfa[4][NB], cfb[4][NB];
    float4 msbA, mssA, msbB, mssB;
    {
        const int ibase = 4 * L;
        #pragma unroll
        for (int q = 0; q < 4; q++) {
            const int sA = oA * IN_DIM + ibase + q;
            const int sB = oB * IN_DIM + ibase + q;
            float4 a0 = *(const float4*)(coef + sA * NB);
            float4 a1 = *(const float4*)(coef + sA * NB + 4);
            cfa[q][0]=a0.x; cfa[q][1]=a0.y; cfa[q][2]=a0.z; cfa[q][3]=a0.w;
            cfa[q][4]=a1.x; cfa[q][5]=a1.y; cfa[q][6]=a1.z; cfa[q][7]=a1.w;
            float4 c0 = *(const float4*)(coef + sB * NB);
            float4 c1 = *(const float4*)(coef + sB * NB + 4);
            cfb[q][0]=c0.x; cfb[q][1]=c0.y; cfb[q][2]=c0.z; cfb[q][3]=c0.w;
            cfb[q][4]=c1.x; cfb[q][5]=c1.y; cfb[q][6]=c1.z; cfb[q][7]=c1.w;
        }
        const float4 sbA = *(const float4*)(scale_base + oA * IN_DIM + ibase);
        const float4 spA = *(const float4*)(scale_sp   + oA * IN_DIM + ibase);
        const float4 mkA = *(const float4*)(mask       + oA * IN_DIM + ibase);
        msbA = make_float4(mkA.x*sbA.x, mkA.y*sbA.y, mkA.z*sbA.z, mkA.w*sbA.w);
        mssA = make_float4(mkA.x*spA.x, mkA.y*spA.y, mkA.z*spA.z, mkA.w*spA.w);
        const float4 sbB = *(const float4*)(scale_base + oB * IN_DIM + ibase);
        const float4 spB = *(const float4*)(scale_sp   + oB * IN_DIM + ibase);
        const float4 mkB = *(const float4*)(mask       + oB * IN_DIM + ibase);
        msbB = make_float4(mkB.x*sbB.x, mkB.y*sbB.y, mkB.z*sbB.z, mkB.w*sbB.w);
        mssB = make_float4(mkB.x*spB.x, mkB.y*spB.y, mkB.z*spB.z, mkB.w*spB.w);
    }

    __syncthreads();

    const size_t P = (size_t)BATCHSZ * OUT_DIM * IN_DIM;
    float* y_out      = out;
    float* preacts    = out + (size_t)BATCHSZ * OUT_DIM;
    float* postacts   = preacts + P;
    float* postspline = postacts + P;

    float v[2 * TILE_B];   // per-lane partials: v[2b]=(b,oA), v[2b+1]=(b,oB)

    #pragma unroll
    for (int b = 0; b < TILE_B; b++) {
        const int bg = b0 + b;

        uint4 hv[4];
        #pragma unroll
        for (int q = 0; q < 4; q++) {
            const int off = (b * IN_DIM + 4 * L + q) * 16;
            hv[q] = *(const uint4*)(Bsh + SW128(off));
        }

        float spa[4], spb[4];
        #pragma unroll
        for (int q = 0; q < 4; q++) {
            const __half2* hh = (const __half2*)&hv[q];
            const float2 f0 = __half22float2(hh[0]);
            const float2 f1 = __half22float2(hh[1]);
            const float2 f2 = __half22float2(hh[2]);
            const float2 f3 = __half22float2(hh[3]);
            float sA, sB;
            sA = cfa[q][0] * f0.x;            sB = cfb[q][0] * f0.x;
            sA = fmaf(cfa[q][1], f0.y, sA);   sB = fmaf(cfb[q][1], f0.y, sB);
            sA = fmaf(cfa[q][2], f1.x, sA);   sB = fmaf(cfb[q][2], f1.x, sB);
            sA = fmaf(cfa[q][3], f1.y, sA);   sB = fmaf(cfb[q][3], f1.y, sB);
            sA = fmaf(cfa[q][4], f2.x, sA);   sB = fmaf(cfb[q][4], f2.x, sB);
            sA = fmaf(cfa[q][5], f2.y, sA);   sB = fmaf(cfb[q][5], f2.y, sB);
            sA = fmaf(cfa[q][6], f3.x, sA);   sB = fmaf(cfb[q][6], f3.x, sB);
            sA = fmaf(cfa[q][7], f3.y, sA);   sB = fmaf(cfb[q][7], f3.y, sB);
            spa[q] = sA; spb[q] = sB;
        }

        const float4 xv = xsh[b][L];
        const float4 sl = ssh[b][L];
        float4 ya, yb;
        ya.x = fmaf(mssA.x, spa[0], msbA.x * sl.x);
        ya.y = fmaf(mssA.y, spa[1], msbA.y * sl.y);
        ya.z = fmaf(mssA.z, spa[2], msbA.z * sl.z);
        ya.w = fmaf(mssA.w, spa[3], msbA.w * sl.w);
        yb.x = fmaf(mssB.x, spb[0], msbB.x * sl.x);
        yb.y = fmaf(mssB.y, spb[1], msbB.y * sl.y);
        yb.z = fmaf(mssB.z, spb[2], msbB.z * sl.z);
        yb.w = fmaf(mssB.w, spb[3], msbB.w * sl.w);

        const size_t baseA = ((size_t)bg * OUT_DIM + oA) * IN_DIM + 4 * L;
        const size_t baseB = ((size_t)bg * OUT_DIM + oB) * IN_DIM + 4 * L;
        const float4 sva = make_float4(spa[0], spa[1], spa[2], spa[3]);
        const float4 svb = make_float4(spb[0], spb[1], spb[2], spb[3]);
        __stcs((float4*)(preacts    + baseA), xv);
        __stcs((float4*)(postacts   + baseA), ya);
        __stcs((float4*)(postspline + baseA), sva);
        __stcs((float4*)(preacts    + baseB), xv);
        __stcs((float4*)(postacts   + baseB), yb);
        __stcs((float4*)(postspline + baseB), svb);

        v[2 * b]     = (ya.x + ya.y) + (ya.z + ya.w);
        v[2 * b + 1] = (yb.x + yb.y) + (yb.z + yb.w);
    }

    // ---- multi-value butterfly: 16 partials reduced with 16 shuffles ----
    // v index m bits: m0 = t (0->oA,1->oB), m1 = b0, m2 = b1, m3 = b2.
    // step (lane-bit d, half n/2): keep lo if (L&d)==0 else hi, swap other.
    #pragma unroll
    for (int m = 0; m < 8; m++) {                       // d=1, n=16 (splits b2)
        const float lo = v[m], hi = v[m + 8];
        const float send = (L & 1) ? lo : hi;
        const float recv = __shfl_xor_sync(0xffffffffu, send, 1);
        v[m] = ((L & 1) ? hi : lo) + recv;
    }
    #pragma unroll
    for (int m = 0; m < 4; m++) {                       // d=2 (splits b1)
        const float lo = v[m], hi = v[m + 4];
        const float send = (L & 2) ? lo : hi;
        const float recv = __shfl_xor_sync(0xffffffffu, send, 2);
        v[m] = ((L & 2) ? hi : lo) + recv;
    }
    #pragma unroll
    for (int m = 0; m < 2; m++) {                       // d=4 (splits b0)
        const float lo = v[m], hi = v[m + 2];
        const float send = (L & 4) ? lo : hi;
        const float recv = __shfl_xor_sync(0xffffffffu, send, 4);
        v[m] = ((L & 4) ? hi : lo) + recv;
    }
    {                                                   // d=8 (splits t)
        const float lo = v[0], hi = v[1];
        const float send = (L & 8) ? lo : hi;
        const float recv = __shfl_xor_sync(0xffffffffu, send, 8);
        v[0] = ((L & 8) ? hi : lo) + recv;
    }
    v[0] += __shfl_xor_sync(0xffffffffu, v[0], 16);     // d=16 (same index)

    if (L < 16) {
        const int t  = (L >> 3) & 1;
        const int bl = ((L & 1) << 2) | (L & 2) | ((L >> 2) & 1); // b2 b1 b0
        const int o  = t ? oB : oA;
        y_out[(b0 + bl) * OUT_DIM + o] = v[0];
    }
}

// ---------------------------------------------------------------------------
extern "C" void kernel_launch(void* const* d_in, const int* in_sizes, int n_in,
                              void* d_out, int out_size)
{
    const float* x          = (const float*)d_in[0];
    const float* grid       = (const float*)d_in[1];
    const float* coef       = (const float*)d_in[2];
    const float* scale_base = (const float*)d_in[3];
    const float* scale_sp   = (const float*)d_in[4];
    const float* mask       = (const float*)d_in[5];
    float* out = (float*)d_out;

    kan_basis_kernel<<<(BATCHSZ * IN_DIM + 255) / 256, 256>>>(x, grid);

    dim3 g(BATCHSZ / TILE_B, OUT_DIM / 16);
    kan_main_kernel<<<g, NTHREADS>>>(x, coef, scale_base, scale_sp, mask, out);
}